// round 13
// baseline (speedup 1.0000x reference)
#include <cuda_runtime.h>
#include <cuda_fp16.h>
#include <math.h>
#include <stdint.h>

// Problem constants
#define NTOK   16384
#define DIM    1024
#define HID    2048
#define NEXP   8
#define CAP    4096

// ---------------- scratch (static device globals; no allocation) -------------
__device__ float    g_scoresT[NEXP * NTOK];
__device__ int      g_sel_idx[NEXP * CAP];
__device__ float    g_sel_scale[NEXP * CAP];
__device__ uint32_t g_thr_bits[NEXP];
__device__ int      g_thr_b4[NEXP];
__device__ int      g_thr_c5[NEXP];
__device__ int      g_cnt[NEXP];
__device__ __half   g_xh[(size_t)NEXP * CAP * DIM];       // routed activations
__device__ __half   g_w13t[(size_t)NEXP * 2 * HID * DIM]; // [e][n'=4096][k=1024]
__device__ __half   g_w2t[(size_t)NEXP * DIM * HID];      // [e][n=1024][k=2048]
__device__ __half   g_hh[(size_t)NEXP * CAP * HID];       // h

// ============================ PTX helpers ====================================
__device__ __forceinline__ uint32_t smem_to_u32(const void* p) {
    uint32_t a;
    asm("{ .reg .u64 t; cvta.to.shared.u64 t, %1; cvt.u32.u64 %0, t; }"
        : "=r"(a) : "l"(p));
    return a;
}

#define CP_ASYNC16(smem_u32, gptr) \
    asm volatile("cp.async.cg.shared.global [%0], [%1], 16;" \
                 :: "r"(smem_u32), "l"(gptr) : "memory")
#define CP_COMMIT() asm volatile("cp.async.commit_group;" ::: "memory")
#define CP_WAIT2()  asm volatile("cp.async.wait_group 2;" ::: "memory")

#define LDMX4(r0, r1, r2, r3, addr) \
    asm volatile("ldmatrix.sync.aligned.m8n8.x4.shared.b16 {%0,%1,%2,%3}, [%4];" \
                 : "=r"(r0), "=r"(r1), "=r"(r2), "=r"(r3) : "r"(addr))

#define MMA16816(d, a, b) \
    asm volatile("mma.sync.aligned.m16n8k16.row.col.f32.f16.f16.f32 " \
                 "{%0,%1,%2,%3}, {%4,%5,%6,%7}, {%8,%9}, {%0,%1,%2,%3};" \
                 : "+f"((d)[0]), "+f"((d)[1]), "+f"((d)[2]), "+f"((d)[3]) \
                 : "r"((a)[0]), "r"((a)[1]), "r"((a)[2]), "r"((a)[3]), \
                   "r"((b)[0]), "r"((b)[1]))

// smem tile geometry: padded rows of 40 halves (80 B) -> conflict-free ldmatrix
#define ROWB   80
#define A_SZ   (128 * ROWB)            // 10240 B : 128x32 fp16 tile
#define B_SZ   (256 * ROWB)            // 20480 B : 256x32 fp16 tile
#define STG    (A_SZ + B_SZ)           // 30720 B per stage
#define STAGES 4
#define DSM_GEMM (STAGES * STG)        // 122880 B -> 1 CTA/SM

// ---------------- zero output -------------------------------------------------
__global__ void zero_kernel(float* out, int n4) {
    float4 z = make_float4(0.f, 0.f, 0.f, 0.f);
    for (int i = blockIdx.x * blockDim.x + threadIdx.x; i < n4;
         i += gridDim.x * blockDim.x)
        ((float4*)out)[i] = z;
}

// ---------------- router (wg staged transposed in smem) -----------------------
__global__ void router_kernel(const float* __restrict__ x,
                              const float* __restrict__ wg) {
    __shared__ float swg[NEXP * DIM];
    int tid = threadIdx.x;
    for (int i = tid; i < NEXP * DIM; i += blockDim.x) {
        int k = i >> 3, e = i & 7;
        swg[e * DIM + k] = wg[i];
    }
    __syncthreads();

    int warp  = tid >> 5;
    int lane  = tid & 31;
    int token = blockIdx.x * (blockDim.x >> 5) + warp;
    if (token >= NTOK) return;

    const float* xr = x + (size_t)token * DIM;
    float acc[NEXP];
#pragma unroll
    for (int e = 0; e < NEXP; e++) acc[e] = 0.f;
    for (int k = lane; k < DIM; k += 32) {
        float xv = xr[k];
#pragma unroll
        for (int e = 0; e < NEXP; e++) acc[e] += xv * swg[e * DIM + k];
    }
#pragma unroll
    for (int off = 16; off > 0; off >>= 1)
#pragma unroll
        for (int e = 0; e < NEXP; e++)
            acc[e] += __shfl_down_sync(0xffffffffu, acc[e], off);
    if (lane == 0) {
        float m = acc[0];
#pragma unroll
        for (int e = 1; e < NEXP; e++) m = fmaxf(m, acc[e]);
        float s = 0.f;
#pragma unroll
        for (int e = 0; e < NEXP; e++) { acc[e] = expf(acc[e] - m); s += acc[e]; }
        float inv = 1.f / s;
#pragma unroll
        for (int e = 0; e < NEXP; e++)
            g_scoresT[e * NTOK + token] = acc[e] * inv;
    }
}

// ---------------- exact top-CAP selection via multi-level radix ---------------
__device__ __forceinline__ void find_cut_desc(const uint32_t* hist, int nb,
                                              int cap, uint32_t* csum, int* res) {
    int tid = threadIdx.x;
    int cs = nb / 32;
    if (tid < 32) {
        uint32_t s = 0;
        for (int i = 0; i < cs; i++) s += hist[tid * cs + i];
        csum[tid] = s;
    }
    __syncthreads();
    if (tid == 0) {
        int acc = 0;
        for (int c = 31; c >= 0; c--) {
            if (acc + (int)csum[c] >= cap) {
                for (int b = c * cs + cs - 1; b >= c * cs; b--) {
                    acc += (int)hist[b];
                    if (acc >= cap) {
                        res[0] = b; res[1] = cap - (acc - (int)hist[b]);
                        break;
                    }
                }
                break;
            }
            acc += (int)csum[c];
        }
    }
    __syncthreads();
}

__device__ __forceinline__ void find_cut_asc(const uint32_t* hist, int nb,
                                             int cap, uint32_t* csum, int* res) {
    int tid = threadIdx.x;
    int cs = nb / 32;
    if (tid < 32) {
        uint32_t s = 0;
        for (int i = 0; i < cs; i++) s += hist[tid * cs + i];
        csum[tid] = s;
    }
    __syncthreads();
    if (tid == 0) {
        int acc = 0;
        for (int c = 0; c < 32; c++) {
            if (acc + (int)csum[c] >= cap) {
                for (int b = c * cs; b < c * cs + cs; b++) {
                    acc += (int)hist[b];
                    if (acc >= cap) {
                        res[0] = b; res[1] = cap - (acc - (int)hist[b]);
                        break;
                    }
                }
                break;
            }
            acc += (int)csum[c];
        }
    }
    __syncthreads();
}

__global__ void select_thresh_kernel() {
    __shared__ uint32_t hist[4096];
    __shared__ uint32_t csum[32];
    __shared__ int res[2];
    int e = blockIdx.x;
    int tid = threadIdx.x;                    // 1024 threads
    const float* s = g_scoresT + (size_t)e * NTOK;

    for (int i = tid; i < 4096; i += 1024) hist[i] = 0;
    __syncthreads();
    for (int i = tid; i < NTOK; i += 1024)
        atomicAdd(&hist[__float_as_uint(s[i]) >> 20], 1u);
    __syncthreads();
    find_cut_desc(hist, 4096, CAP, csum, res);
    int T1 = res[0], r1 = res[1];
    __syncthreads();

    for (int i = tid; i < 4096; i += 1024) hist[i] = 0;
    __syncthreads();
    for (int i = tid; i < NTOK; i += 1024) {
        uint32_t b = __float_as_uint(s[i]);
        if ((int)(b >> 20) == T1) atomicAdd(&hist[(b >> 8) & 0xFFF], 1u);
    }
    __syncthreads();
    find_cut_desc(hist, 4096, r1, csum, res);
    int T2 = res[0], r2 = res[1];
    __syncthreads();

    uint32_t pfx = ((uint32_t)T1 << 12) | (uint32_t)T2;
    for (int i = tid; i < 256; i += 1024) hist[i] = 0;
    __syncthreads();
    for (int i = tid; i < NTOK; i += 1024) {
        uint32_t b = __float_as_uint(s[i]);
        if ((b >> 8) == pfx) atomicAdd(&hist[b & 0xFF], 1u);
    }
    __syncthreads();
    find_cut_desc(hist, 256, r2, csum, res);
    int T3 = res[0], r3 = res[1];
    __syncthreads();

    uint32_t thr = (pfx << 8) | (uint32_t)T3;
    for (int i = tid; i < 128; i += 1024) hist[i] = 0;
    __syncthreads();
    for (int i = tid; i < NTOK; i += 1024)
        if (__float_as_uint(s[i]) == thr) atomicAdd(&hist[i >> 7], 1u);
    __syncthreads();
    find_cut_asc(hist, 128, r3, csum, res);
    int B4 = res[0], r4 = res[1];
    __syncthreads();

    for (int i = tid; i < 128; i += 1024) hist[i] = 0;
    __syncthreads();
    for (int i = tid; i < NTOK; i += 1024)
        if (__float_as_uint(s[i]) == thr && (i >> 7) == B4)
            atomicAdd(&hist[i & 127], 1u);
    __syncthreads();
    find_cut_asc(hist, 128, r4, csum, res);
    int C5 = res[0];

    if (tid == 0) {
        g_thr_bits[e] = thr;
        g_thr_b4[e]   = B4;
        g_thr_c5[e]   = C5;
        g_cnt[e]      = 0;
    }
}

__global__ void compact_kernel() {
    int gid = blockIdx.x * blockDim.x + threadIdx.x;
    if (gid >= NEXP * NTOK) return;
    int e = gid >> 14, idx = gid & (NTOK - 1);
    uint32_t b = __float_as_uint(g_scoresT[(size_t)e * NTOK + idx]);
    uint32_t thr = g_thr_bits[e];
    bool sel = b > thr;
    if (!sel && b == thr) {
        int hi = idx >> 7, lo = idx & 127;
        sel = (hi < g_thr_b4[e]) || (hi == g_thr_b4[e] && lo <= g_thr_c5[e]);
    }
    if (sel) {
        int p = atomicAdd(&g_cnt[e], 1);
        g_sel_idx[e * CAP + p]   = idx;
        g_sel_scale[e * CAP + p] = __uint_as_float(b);
    }
}

// ---------------- gather + scale -> fp16 --------------------------------------
__global__ void gather_convert_kernel(const float* __restrict__ x) {
    int row = blockIdx.x;
    int tok = g_sel_idx[row];
    float sc = g_sel_scale[row];
    const float4* src = (const float4*)(x + (size_t)tok * DIM);
    __half* ph = g_xh + (size_t)row * DIM;
    int i = threadIdx.x;
    float4 a = src[2 * i], b = src[2 * i + 1];
    float v[8] = {a.x, a.y, a.z, a.w, b.x, b.y, b.z, b.w};
    __align__(16) __half hb[8];
#pragma unroll
    for (int t = 0; t < 8; t++) hb[t] = __float2half_rn(v[t] * sc);
    *(uint4*)(ph + 8 * i) = *(uint4*)hb;
}

// ---------------- weight transpose+convert ------------------------------------
// w1,w3 -> g_w13t [e][n'][k], n' packed in 64-blocks: (32 w1 cols, 32 w3 cols)
__global__ void convert_w13_kernel(const float* __restrict__ w1,
                                   const float* __restrict__ w3) {
    __shared__ float t1[32][33], t3[32][33];
    int e = blockIdx.z;
    int n0 = blockIdx.x * 32;
    int k0 = blockIdx.y * 32;
    const float* s1 = w1 + (size_t)e * DIM * HID;
    const float* s3 = w3 + (size_t)e * DIM * HID;
    int tx = threadIdx.x, ty = threadIdx.y;
    for (int i = ty; i < 32; i += 8) {
        t1[i][tx] = s1[(size_t)(k0 + i) * HID + n0 + tx];
        t3[i][tx] = s3[(size_t)(k0 + i) * HID + n0 + tx];
    }
    __syncthreads();
    for (int j = ty; j < 32; j += 8) {
        int n = n0 + j;
        int np1 = (n >> 5) * 64 + (n & 31);
        int np3 = np1 + 32;
        g_w13t[((size_t)e * 4096 + np1) * DIM + k0 + tx] = __float2half_rn(t1[tx][j]);
        g_w13t[((size_t)e * 4096 + np3) * DIM + k0 + tx] = __float2half_rn(t3[tx][j]);
    }
}

__global__ void convert_w2_kernel(const float* __restrict__ w2) {
    __shared__ float t[32][33];
    int e = blockIdx.z;
    int n0 = blockIdx.x * 32;
    int k0 = blockIdx.y * 32;
    const float* s = w2 + (size_t)e * HID * DIM;
    int tx = threadIdx.x, ty = threadIdx.y;
    for (int i = ty; i < 32; i += 8)
        t[i][tx] = s[(size_t)(k0 + i) * DIM + n0 + tx];
    __syncthreads();
    for (int j = ty; j < 32; j += 8)
        g_w2t[((size_t)e * DIM + n0 + j) * HID + k0 + tx] = __float2half_rn(t[tx][j]);
}

// ---------------- mma.sync GEMM core (256 threads, BM=128, BN=256) ------------
__device__ __forceinline__ void load_stage(
    uint32_t sm, const __half* __restrict__ A, const __half* __restrict__ Bp,
    int ldK, int kb, int tid)
{
    uint32_t smA = sm, smB = sm + A_SZ;
#pragma unroll
    for (int i = 0; i < 2; i++) {            // A: 128x32 = 512 float4s
        int c = tid + i * 256;
        int row = c >> 2, seg = c & 3;
        CP_ASYNC16(smA + row * ROWB + seg * 16,
                   A + (size_t)row * ldK + kb + seg * 8);
    }
#pragma unroll
    for (int i = 0; i < 4; i++) {            // B: 256x32 = 1024 float4s
        int c = tid + i * 256;
        int row = c >> 2, seg = c & 3;
        CP_ASYNC16(smB + row * ROWB + seg * 16,
                   Bp + (size_t)row * ldK + kb + seg * 8);
    }
}

// Warp tile 32x128: 2 m-frags x 16 n-frags. B fragments are loaded and
// consumed per ldmatrix.x4 (2 n-frags live at a time) to bound register use.
__device__ __forceinline__ void mma_compute_stage(
    uint32_t sm, int lane, int warp_m, int warp_n, float acc[2][16][4])
{
    uint32_t smA = sm, smB = sm + A_SZ;
#pragma unroll
    for (int ks = 0; ks < 2; ks++) {
        uint32_t ah[2][4];
#pragma unroll
        for (int mi = 0; mi < 2; mi++) {
            uint32_t off = (warp_m * 32 + mi * 16 + (lane & 15)) * ROWB
                         + (ks * 16 + (lane >> 4) * 8) * 2;
            LDMX4(ah[mi][0], ah[mi][1], ah[mi][2], ah[mi][3], smA + off);
        }
#pragma unroll
        for (int p = 0; p < 8; p++) {        // 2 n-frags per ldmatrix.x4
            uint32_t addr = smB + (warp_n * 128 + p * 16 + (lane & 15)) * ROWB
                          + (ks * 16 + (lane >> 4) * 8) * 2;
            uint32_t r0, r1, r2, r3;
            LDMX4(r0, r1, r2, r3, addr);
            uint32_t b0[2] = {r0, r2};
            uint32_t b1[2] = {r1, r3};
#pragma unroll
            for (int mi = 0; mi < 2; mi++) {
                MMA16816(acc[mi][2 * p],     ah[mi], b0);
                MMA16816(acc[mi][2 * p + 1], ah[mi], b1);
            }
        }
    }
}

// Single-sync multistage loop: per chunk
// [load kt+S-1] [commit] [compute kt] [wait <=S-2] [sync].
template <int KT>
__device__ __forceinline__ void mma_mainloop(
    uint32_t sm, const __half* A, const __half* Bp,
    int ldK, int tid, int lane, int warp_m, int warp_n, float acc[2][16][4])
{
#pragma unroll
    for (int s = 0; s < STAGES - 1; s++) {
        load_stage(sm + s * STG, A, Bp, ldK, s * 32, tid);
        CP_COMMIT();
    }
    CP_WAIT2();
    __syncthreads();
    for (int kt = 0; kt < KT; kt++) {
        int lt = kt + STAGES - 1;
        if (lt < KT)
            load_stage(sm + (lt % STAGES) * STG, A, Bp, ldK, lt * 32, tid);
        CP_COMMIT();
        mma_compute_stage(sm + (kt % STAGES) * STG, lane, warp_m, warp_n, acc);
        CP_WAIT2();
        __syncthreads();
    }
}

// ---------------- GEMM13: h = silu(X@W1) * (X@W3) -> fp16 ---------------------
__global__ __launch_bounds__(256)
void gemm13_mma_kernel() {
    extern __shared__ char dsm[];
    uint32_t sm = smem_to_u32(dsm);
    int tid = threadIdx.x, lane = tid & 31, wid = tid >> 5;
    int warp_m = wid & 3, warp_n = wid >> 2;           // 4m x 2n
    int e = blockIdx.z, mBase = blockIdx.y * 128, nBase = blockIdx.x * 256;

    const __half* A  = g_xh + ((size_t)e * CAP + mBase) * DIM;
    const __half* Bp = g_w13t + ((size_t)e * 4096 + nBase) * DIM;

    float acc[2][16][4];
#pragma unroll
    for (int i = 0; i < 2; i++)
#pragma unroll
        for (int j = 0; j < 16; j++)
#pragma unroll
            for (int q = 0; q < 4; q++) acc[i][j][q] = 0.f;

    mma_mainloop<DIM / 32>(sm, A, Bp, DIM, tid, lane, warp_m, warp_n, acc);

    // SwiGLU epilogue. Warp covers 128 n'-cols = two 64-blocks.
    // Block group g (ni 0-7 / 8-15): ni g*8+0..3 = s1 cols, +4 = s3 cols.
    int hbase = (nBase + warp_n * 128) >> 1;
    int m0 = mBase + warp_m * 32;
#pragma unroll
    for (int mi = 0; mi < 2; mi++)
#pragma unroll
        for (int g = 0; g < 2; g++)
#pragma unroll
            for (int nj = 0; nj < 4; nj++) {
                int ni = g * 8 + nj;
                int hc = hbase + g * 32 + 8 * nj + 2 * (lane & 3);
#pragma unroll
                for (int h2 = 0; h2 < 2; h2++) {
                    int m = m0 + mi * 16 + (lane >> 2) + h2 * 8;
                    float s1a = acc[mi][ni][2 * h2];
                    float s1b = acc[mi][ni][2 * h2 + 1];
                    float s3a = acc[mi][ni + 4][2 * h2];
                    float s3b = acc[mi][ni + 4][2 * h2 + 1];
                    float ha = s1a * s3a / (1.f + expf(-s1a));
                    float hb = s1b * s3b / (1.f + expf(-s1b));
                    size_t off = ((size_t)e * CAP + m) * HID + hc;
                    *(__half2*)(g_hh + off) =
                        __halves2half2(__float2half_rn(ha), __float2half_rn(hb));
                }
            }
}

// ---------------- GEMM2: out[token] += H@W2 (scatter-add) ---------------------
__global__ __launch_bounds__(256)
void gemm2_mma_kernel(float* __restrict__ out) {
    extern __shared__ char dsm[];
    uint32_t sm = smem_to_u32(dsm);
    int tid = threadIdx.x, lane = tid & 31, wid = tid >> 5;
    int warp_m = wid & 3, warp_n = wid >> 2;
    int e = blockIdx.z, mBase = blockIdx.y * 128, nBase = blockIdx.x * 256;

    const __half* A  = g_hh + ((size_t)e * CAP + mBase) * HID;
    const __half* Bp = g_w2t + ((size_t)e * DIM + nBase) * HID;

    float acc[2][16][4];
#pragma unroll
    for (int i = 0; i < 2; i++)
#pragma unroll
        for (int j = 0; j < 16; j++)
#pragma unroll
            for (int q = 0; q < 4; q++) acc[i][j][q] = 0.f;

    mma_mainloop<HID / 32>(sm, A, Bp, HID, tid, lane, warp_m, warp_n, acc);

    int n0 = nBase + warp_n * 128;
    int m0 = mBase + warp_m * 32;
#pragma unroll
    for (int mi = 0; mi < 2; mi++)
#pragma unroll
        for (int h2 = 0; h2 < 2; h2++) {
            int c = m0 + mi * 16 + (lane >> 2) + h2 * 8;
            int tok = g_sel_idx[e * CAP + c];
            float* orow = out + (size_t)tok * DIM;
#pragma unroll
            for (int ni = 0; ni < 16; ni++) {
                int n = n0 + 8 * ni + 2 * (lane & 3);
                atomicAdd(&orow[n],     acc[mi][ni][2 * h2]);
                atomicAdd(&orow[n + 1], acc[mi][ni][2 * h2 + 1]);
            }
        }
}

// ---------------- launch ------------------------------------------------------
extern "C" void kernel_launch(void* const* d_in, const int* in_sizes, int n_in,
                              void* d_out, int out_size) {
    const float* x  = (const float*)d_in[0];
    const float* wg = (const float*)d_in[1];
    const float* w1 = (const float*)d_in[2];
    const float* w3 = (const float*)d_in[3];
    const float* w2 = (const float*)d_in[4];
    float* out = (float*)d_out;

    cudaFuncSetAttribute(gemm13_mma_kernel,
                         cudaFuncAttributeMaxDynamicSharedMemorySize, DSM_GEMM);
    cudaFuncSetAttribute(gemm2_mma_kernel,
                         cudaFuncAttributeMaxDynamicSharedMemorySize, DSM_GEMM);

    zero_kernel<<<4096, 256>>>(out, NTOK * DIM / 4);
    convert_w13_kernel<<<dim3(HID / 32, DIM / 32, NEXP), dim3(32, 8)>>>(w1, w3);
    convert_w2_kernel<<<dim3(DIM / 32, HID / 32, NEXP), dim3(32, 8)>>>(w2);
    router_kernel<<<NTOK / 8, 256>>>(x, wg);
    select_thresh_kernel<<<NEXP, 1024>>>();
    compact_kernel<<<NEXP * NTOK / 256, 256>>>();
    gather_convert_kernel<<<NEXP * CAP, 128>>>(x);
    gemm13_mma_kernel<<<dim3(4096 / 256, CAP / 128, NEXP), 256, DSM_GEMM>>>();
    gemm2_mma_kernel<<<dim3(DIM / 256, CAP / 128, NEXP), 256, DSM_GEMM>>>(out);
}

// round 17
// speedup vs baseline: 1.0631x; 1.0631x over previous
#include <cuda_runtime.h>
#include <cuda_fp16.h>
#include <math.h>
#include <stdint.h>

// Problem constants
#define NTOK   16384
#define DIM    1024
#define HID    2048
#define NEXP   8
#define CAP    4096

// ---------------- scratch (static device globals; no allocation) -------------
__device__ float    g_scoresT[NEXP * NTOK];
__device__ int      g_sel_idx[NEXP * CAP];
__device__ float    g_sel_scale[NEXP * CAP];
__device__ __half   g_xh[(size_t)NEXP * CAP * DIM];       // routed activations
__device__ __half   g_w13t[(size_t)NEXP * 2 * HID * DIM]; // [e][n'=4096][k=1024]
__device__ __half   g_w2t[(size_t)NEXP * DIM * HID];      // [e][n=1024][k=2048]
__device__ __half   g_hh[(size_t)NEXP * CAP * HID];       // h

// ============================ PTX helpers ====================================
__device__ __forceinline__ uint32_t smem_to_u32(const void* p) {
    uint32_t a;
    asm("{ .reg .u64 t; cvta.to.shared.u64 t, %1; cvt.u32.u64 %0, t; }"
        : "=r"(a) : "l"(p));
    return a;
}

#define CP_ASYNC16(smem_u32, gptr) \
    asm volatile("cp.async.cg.shared.global [%0], [%1], 16;" \
                 :: "r"(smem_u32), "l"(gptr) : "memory")
#define CP_COMMIT() asm volatile("cp.async.commit_group;" ::: "memory")
#define CP_WAIT2()  asm volatile("cp.async.wait_group 2;" ::: "memory")

#define LDMX4(r0, r1, r2, r3, addr) \
    asm volatile("ldmatrix.sync.aligned.m8n8.x4.shared.b16 {%0,%1,%2,%3}, [%4];" \
                 : "=r"(r0), "=r"(r1), "=r"(r2), "=r"(r3) : "r"(addr))

#define MMA16816(d, a, b) \
    asm volatile("mma.sync.aligned.m16n8k16.row.col.f32.f16.f16.f32 " \
                 "{%0,%1,%2,%3}, {%4,%5,%6,%7}, {%8,%9}, {%0,%1,%2,%3};" \
                 : "+f"((d)[0]), "+f"((d)[1]), "+f"((d)[2]), "+f"((d)[3]) \
                 : "r"((a)[0]), "r"((a)[1]), "r"((a)[2]), "r"((a)[3]), \
                   "r"((b)[0]), "r"((b)[1]))

// smem tile geometry: padded rows of 40 halves (80 B) -> conflict-free ldmatrix
#define ROWB   80
#define A_SZ   (128 * ROWB)            // 10240 B per 128x32 fp16 tile
#define STG    (2 * A_SZ)              // A, B per stage
#define STAGES 4
#define DSM_GEMM (STAGES * STG)        // 81920 B -> 2 CTAs/SM

// ---------------- merged prep kernel -----------------------------------------
// Independent work fused into one launch, branch on blockIdx range:
//   [0, 2048)        : zero out
//   [2048, 4096)     : router (code bit-identical to the proven kernel)
//   [4096, 20480)    : convert w1/w3 -> g_w13t
//   [20480, 36864)   : convert w2    -> g_w2t
#define MB_ZERO   2048
#define MB_ROUTER 2048
#define MB_W13    16384
#define MB_W2     16384
#define MB_TOTAL  (MB_ZERO + MB_ROUTER + MB_W13 + MB_W2)

__global__ __launch_bounds__(256)
void prep_kernel(const float* __restrict__ x,  const float* __restrict__ wg,
                 const float* __restrict__ w1, const float* __restrict__ w3,
                 const float* __restrict__ w2, float* __restrict__ out) {
    __shared__ __align__(16) char smem_u[NEXP * DIM * 4];   // 32 KB union
    int bid = blockIdx.x;
    int tid = threadIdx.x;

    if (bid < MB_ZERO) {
        // ---- zero out ----
        int n4 = NTOK * DIM / 4;
        float4 z = make_float4(0.f, 0.f, 0.f, 0.f);
        for (int i = bid * 256 + tid; i < n4; i += MB_ZERO * 256)
            ((float4*)out)[i] = z;
        return;
    }
    if (bid < MB_ZERO + MB_ROUTER) {
        // ---- router: BIT-IDENTICAL to the proven standalone kernel ----
        float* swg = (float*)smem_u;
        for (int i = tid; i < NEXP * DIM; i += blockDim.x) {
            int k = i >> 3, e = i & 7;
            swg[e * DIM + k] = wg[i];
        }
        __syncthreads();

        int warp  = tid >> 5;
        int lane  = tid & 31;
        int token = (bid - MB_ZERO) * (blockDim.x >> 5) + warp;
        if (token >= NTOK) return;

        const float* xr = x + (size_t)token * DIM;
        float acc[NEXP];
#pragma unroll
        for (int e = 0; e < NEXP; e++) acc[e] = 0.f;
        for (int k = lane; k < DIM; k += 32) {
            float xv = xr[k];
#pragma unroll
            for (int e = 0; e < NEXP; e++) acc[e] += xv * swg[e * DIM + k];
        }
#pragma unroll
        for (int off = 16; off > 0; off >>= 1)
#pragma unroll
            for (int e = 0; e < NEXP; e++)
                acc[e] += __shfl_down_sync(0xffffffffu, acc[e], off);
        if (lane == 0) {
            float m = acc[0];
#pragma unroll
            for (int e = 1; e < NEXP; e++) m = fmaxf(m, acc[e]);
            float s = 0.f;
#pragma unroll
            for (int e = 0; e < NEXP; e++) { acc[e] = expf(acc[e] - m); s += acc[e]; }
            float inv = 1.f / s;
#pragma unroll
            for (int e = 0; e < NEXP; e++)
                g_scoresT[e * NTOK + token] = acc[e] * inv;
        }
        return;
    }
    if (bid < MB_ZERO + MB_ROUTER + MB_W13) {
        // ---- w1,w3 -> g_w13t [e][n'][k], n' in 64-blocks (32 w1 | 32 w3) ----
        float (*t1)[33] = (float(*)[33])smem_u;
        float (*t3)[33] = (float(*)[33])(smem_u + 32 * 33 * 4);
        int wb = bid - (MB_ZERO + MB_ROUTER);
        int e = wb >> 11;                 // 2048 blocks per expert
        int rem = wb & 2047;
        int n0 = (rem & 63) * 32;         // 64 n-blocks
        int k0 = (rem >> 6) * 32;         // 32 k-blocks
        const float* s1 = w1 + (size_t)e * DIM * HID;
        const float* s3 = w3 + (size_t)e * DIM * HID;
        int tx = tid & 31, ty = tid >> 5;
        for (int i = ty; i < 32; i += 8) {
            t1[i][tx] = s1[(size_t)(k0 + i) * HID + n0 + tx];
            t3[i][tx] = s3[(size_t)(k0 + i) * HID + n0 + tx];
        }
        __syncthreads();
        for (int j = ty; j < 32; j += 8) {
            int n = n0 + j;
            int np1 = (n >> 5) * 64 + (n & 31);
            int np3 = np1 + 32;
            g_w13t[((size_t)e * 4096 + np1) * DIM + k0 + tx] = __float2half_rn(t1[tx][j]);
            g_w13t[((size_t)e * 4096 + np3) * DIM + k0 + tx] = __float2half_rn(t3[tx][j]);
        }
        return;
    }
    {
        // ---- w2 -> g_w2t [e][n][k] ----
        float (*t)[33] = (float(*)[33])smem_u;
        int vb = bid - (MB_ZERO + MB_ROUTER + MB_W13);
        int e = vb >> 11;
        int rem = vb & 2047;
        int n0 = (rem & 31) * 32;         // 32 n-blocks
        int k0 = (rem >> 5) * 32;         // 64 k-blocks
        const float* s = w2 + (size_t)e * HID * DIM;
        int tx = tid & 31, ty = tid >> 5;
        for (int i = ty; i < 32; i += 8)
            t[i][tx] = s[(size_t)(k0 + i) * DIM + n0 + tx];
        __syncthreads();
        for (int j = ty; j < 32; j += 8)
            g_w2t[((size_t)e * DIM + n0 + j) * HID + k0 + tx] = __float2half_rn(t[tx][j]);
    }
}

// ---------------- exact top-CAP selection + in-block compaction ---------------
// Threshold math BIT-IDENTICAL to the proven select_thresh_kernel; compaction
// (formerly a separate kernel) appended in-block with an smem counter. Row
// order within an expert is irrelevant (rows are independent; each carries its
// own token index + scale).
__device__ __forceinline__ void find_cut_desc(const uint32_t* hist, int nb,
                                              int cap, uint32_t* csum, int* res) {
    int tid = threadIdx.x;
    int cs = nb / 32;
    if (tid < 32) {
        uint32_t s = 0;
        for (int i = 0; i < cs; i++) s += hist[tid * cs + i];
        csum[tid] = s;
    }
    __syncthreads();
    if (tid == 0) {
        int acc = 0;
        for (int c = 31; c >= 0; c--) {
            if (acc + (int)csum[c] >= cap) {
                for (int b = c * cs + cs - 1; b >= c * cs; b--) {
                    acc += (int)hist[b];
                    if (acc >= cap) {
                        res[0] = b; res[1] = cap - (acc - (int)hist[b]);
                        break;
                    }
                }
                break;
            }
            acc += (int)csum[c];
        }
    }
    __syncthreads();
}

__device__ __forceinline__ void find_cut_asc(const uint32_t* hist, int nb,
                                             int cap, uint32_t* csum, int* res) {
    int tid = threadIdx.x;
    int cs = nb / 32;
    if (tid < 32) {
        uint32_t s = 0;
        for (int i = 0; i < cs; i++) s += hist[tid * cs + i];
        csum[tid] = s;
    }
    __syncthreads();
    if (tid == 0) {
        int acc = 0;
        for (int c = 0; c < 32; c++) {
            if (acc + (int)csum[c] >= cap) {
                for (int b = c * cs; b < c * cs + cs; b++) {
                    acc += (int)hist[b];
                    if (acc >= cap) {
                        res[0] = b; res[1] = cap - (acc - (int)hist[b]);
                        break;
                    }
                }
                break;
            }
            acc += (int)csum[c];
        }
    }
    __syncthreads();
}

__global__ void select_compact_kernel() {
    __shared__ uint32_t hist[4096];
    __shared__ uint32_t csum[32];
    __shared__ int res[2];
    __shared__ int s_cnt;
    int e = blockIdx.x;
    int tid = threadIdx.x;                    // 1024 threads
    const float* s = g_scoresT + (size_t)e * NTOK;

    for (int i = tid; i < 4096; i += 1024) hist[i] = 0;
    __syncthreads();
    for (int i = tid; i < NTOK; i += 1024)
        atomicAdd(&hist[__float_as_uint(s[i]) >> 20], 1u);
    __syncthreads();
    find_cut_desc(hist, 4096, CAP, csum, res);
    int T1 = res[0], r1 = res[1];
    __syncthreads();

    for (int i = tid; i < 4096; i += 1024) hist[i] = 0;
    __syncthreads();
    for (int i = tid; i < NTOK; i += 1024) {
        uint32_t b = __float_as_uint(s[i]);
        if ((int)(b >> 20) == T1) atomicAdd(&hist[(b >> 8) & 0xFFF], 1u);
    }
    __syncthreads();
    find_cut_desc(hist, 4096, r1, csum, res);
    int T2 = res[0], r2 = res[1];
    __syncthreads();

    uint32_t pfx = ((uint32_t)T1 << 12) | (uint32_t)T2;
    for (int i = tid; i < 256; i += 1024) hist[i] = 0;
    __syncthreads();
    for (int i = tid; i < NTOK; i += 1024) {
        uint32_t b = __float_as_uint(s[i]);
        if ((b >> 8) == pfx) atomicAdd(&hist[b & 0xFF], 1u);
    }
    __syncthreads();
    find_cut_desc(hist, 256, r2, csum, res);
    int T3 = res[0], r3 = res[1];
    __syncthreads();

    uint32_t thr = (pfx << 8) | (uint32_t)T3;
    for (int i = tid; i < 128; i += 1024) hist[i] = 0;
    __syncthreads();
    for (int i = tid; i < NTOK; i += 1024)
        if (__float_as_uint(s[i]) == thr) atomicAdd(&hist[i >> 7], 1u);
    __syncthreads();
    find_cut_asc(hist, 128, r3, csum, res);
    int B4 = res[0], r4 = res[1];
    __syncthreads();

    for (int i = tid; i < 128; i += 1024) hist[i] = 0;
    __syncthreads();
    for (int i = tid; i < NTOK; i += 1024)
        if (__float_as_uint(s[i]) == thr && (i >> 7) == B4)
            atomicAdd(&hist[i & 127], 1u);
    __syncthreads();
    find_cut_asc(hist, 128, r4, csum, res);
    int C5 = res[0];

    // ---- in-block compaction (predicate identical to old compact_kernel) ----
    if (tid == 0) s_cnt = 0;
    __syncthreads();
    for (int idx = tid; idx < NTOK; idx += 1024) {
        uint32_t b = __float_as_uint(s[idx]);
        bool sel = b > thr;
        if (!sel && b == thr) {
            int hi = idx >> 7, lo = idx & 127;
            sel = (hi < B4) || (hi == B4 && lo <= C5);
        }
        if (sel) {
            int p = atomicAdd(&s_cnt, 1);
            g_sel_idx[e * CAP + p]   = idx;
            g_sel_scale[e * CAP + p] = __uint_as_float(b);
        }
    }
}

// ---------------- gather + scale -> fp16 (2 rows per 256-thread block) --------
__global__ __launch_bounds__(256)
void gather_convert_kernel(const float* __restrict__ x) {
    int row = blockIdx.x * 2 + (threadIdx.x >> 7);
    int i   = threadIdx.x & 127;             // 0..127 -> 8 elems each
    int tok = g_sel_idx[row];
    float sc = g_sel_scale[row];
    const float4* src = (const float4*)(x + (size_t)tok * DIM);
    __half* ph = g_xh + (size_t)row * DIM;
    float4 a = src[2 * i], b = src[2 * i + 1];
    float v[8] = {a.x, a.y, a.z, a.w, b.x, b.y, b.z, b.w};
    __align__(16) __half hb[8];
#pragma unroll
    for (int t = 0; t < 8; t++) hb[t] = __float2half_rn(v[t] * sc);
    *(uint4*)(ph + 8 * i) = *(uint4*)hb;
}

// ---------------- mma.sync GEMM core (256 threads, BM=128, BN=128) ------------
__device__ __forceinline__ void load_stage(
    uint32_t sm, const __half* __restrict__ A, const __half* __restrict__ Bp,
    int ldK, int kb, int tid)
{
    uint32_t smA = sm, smB = sm + A_SZ;
#pragma unroll
    for (int i = 0; i < 2; i++) {
        int c = tid + i * 256;               // 0..511
        int row = c >> 2, seg = c & 3;
        size_t g = (size_t)row * ldK + kb + seg * 8;
        uint32_t d = row * ROWB + seg * 16;
        CP_ASYNC16(smA + d, A + g);
        CP_ASYNC16(smB + d, Bp + g);
    }
}

__device__ __forceinline__ void mma_compute_stage(
    uint32_t sm, int lane, int warp_m, int warp_n, float acc[2][8][4])
{
    uint32_t smA = sm, smB = sm + A_SZ;
#pragma unroll
    for (int ks = 0; ks < 2; ks++) {
        uint32_t bf[8][2];
#pragma unroll
        for (int p = 0; p < 4; p++) {
            uint32_t addr = smB + (warp_n * 64 + p * 16 + (lane & 15)) * ROWB
                          + (ks * 16 + (lane >> 4) * 8) * 2;
            uint32_t r0, r1, r2, r3;
            LDMX4(r0, r1, r2, r3, addr);
            bf[2 * p][0] = r0; bf[2 * p + 1][0] = r1;
            bf[2 * p][1] = r2; bf[2 * p + 1][1] = r3;
        }
        uint32_t ah[2][4];
#pragma unroll
        for (int mi = 0; mi < 2; mi++) {
            uint32_t off = (warp_m * 32 + mi * 16 + (lane & 15)) * ROWB
                         + (ks * 16 + (lane >> 4) * 8) * 2;
            LDMX4(ah[mi][0], ah[mi][1], ah[mi][2], ah[mi][3], smA + off);
        }
#pragma unroll
        for (int mi = 0; mi < 2; mi++)
#pragma unroll
            for (int ni = 0; ni < 8; ni++)
                MMA16816(acc[mi][ni], ah[mi], bf[ni]);
    }
}

// Single-sync multistage loop: per chunk
// [load kt+S-1] [commit] [compute kt] [wait <=S-2] [sync].
template <int KT>
__device__ __forceinline__ void mma_mainloop(
    uint32_t sm, const __half* A, const __half* Bp,
    int ldK, int tid, int lane, int warp_m, int warp_n, float acc[2][8][4])
{
#pragma unroll
    for (int s = 0; s < STAGES - 1; s++) {
        load_stage(sm + s * STG, A, Bp, ldK, s * 32, tid);
        CP_COMMIT();
    }
    CP_WAIT2();
    __syncthreads();
    for (int kt = 0; kt < KT; kt++) {
        int lt = kt + STAGES - 1;
        if (lt < KT)
            load_stage(sm + (lt % STAGES) * STG, A, Bp, ldK, lt * 32, tid);
        CP_COMMIT();
        mma_compute_stage(sm + (kt % STAGES) * STG, lane, warp_m, warp_n, acc);
        CP_WAIT2();
        __syncthreads();
    }
}

// ---------------- GEMM13: h = silu(X@W1) * (X@W3) -> fp16 ---------------------
__global__ __launch_bounds__(256)
void gemm13_mma_kernel() {
    extern __shared__ char dsm[];
    uint32_t sm = smem_to_u32(dsm);
    int tid = threadIdx.x, lane = tid & 31, wid = tid >> 5;
    int warp_m = wid & 3, warp_n = wid >> 2;
    int e = blockIdx.z, mBase = blockIdx.y * 128, nBase = blockIdx.x * 128;

    const __half* A  = g_xh + ((size_t)e * CAP + mBase) * DIM;
    const __half* Bp = g_w13t + ((size_t)e * 4096 + nBase) * DIM;

    float acc[2][8][4];
#pragma unroll
    for (int i = 0; i < 2; i++)
#pragma unroll
        for (int j = 0; j < 8; j++)
#pragma unroll
            for (int q = 0; q < 4; q++) acc[i][j][q] = 0.f;

    mma_mainloop<DIM / 32>(sm, A, Bp, DIM, tid, lane, warp_m, warp_n, acc);

    // SwiGLU epilogue: ni in [0,4) = s1 cols, ni+4 = matching s3 cols.
    int hbase = (nBase + warp_n * 64) >> 1;
    int m0 = mBase + warp_m * 32;
#pragma unroll
    for (int mi = 0; mi < 2; mi++)
#pragma unroll
        for (int ni = 0; ni < 4; ni++) {
            int hc = hbase + 8 * ni + 2 * (lane & 3);
#pragma unroll
            for (int h2 = 0; h2 < 2; h2++) {
                int m = m0 + mi * 16 + (lane >> 2) + h2 * 8;
                float s1a = acc[mi][ni][2 * h2];
                float s1b = acc[mi][ni][2 * h2 + 1];
                float s3a = acc[mi][ni + 4][2 * h2];
                float s3b = acc[mi][ni + 4][2 * h2 + 1];
                float ha = s1a * s3a / (1.f + expf(-s1a));
                float hb = s1b * s3b / (1.f + expf(-s1b));
                size_t off = ((size_t)e * CAP + m) * HID + hc;
                *(__half2*)(g_hh + off) =
                    __halves2half2(__float2half_rn(ha), __float2half_rn(hb));
            }
        }
}

// ---------------- GEMM2: out[token] += H@W2 (scatter-add) ---------------------
__global__ __launch_bounds__(256)
void gemm2_mma_kernel(float* __restrict__ out) {
    extern __shared__ char dsm[];
    uint32_t sm = smem_to_u32(dsm);
    int tid = threadIdx.x, lane = tid & 31, wid = tid >> 5;
    int warp_m = wid & 3, warp_n = wid >> 2;
    int e = blockIdx.z, mBase = blockIdx.y * 128, nBase = blockIdx.x * 128;

    const __half* A  = g_hh + ((size_t)e * CAP + mBase) * HID;
    const __half* Bp = g_w2t + ((size_t)e * DIM + nBase) * HID;

    float acc[2][8][4];
#pragma unroll
    for (int i = 0; i < 2; i++)
#pragma unroll
        for (int j = 0; j < 8; j++)
#pragma unroll
            for (int q = 0; q < 4; q++) acc[i][j][q] = 0.f;

    mma_mainloop<HID / 32>(sm, A, Bp, HID, tid, lane, warp_m, warp_n, acc);

    int n0 = nBase + warp_n * 64;
    int m0 = mBase + warp_m * 32;
#pragma unroll
    for (int mi = 0; mi < 2; mi++)
#pragma unroll
        for (int h2 = 0; h2 < 2; h2++) {
            int c = m0 + mi * 16 + (lane >> 2) + h2 * 8;
            int tok = g_sel_idx[e * CAP + c];
            float* orow = out + (size_t)tok * DIM;
#pragma unroll
            for (int ni = 0; ni < 8; ni++) {
                int n = n0 + 8 * ni + 2 * (lane & 3);
                atomicAdd(&orow[n],     acc[mi][ni][2 * h2]);
                atomicAdd(&orow[n + 1], acc[mi][ni][2 * h2 + 1]);
            }
        }
}

// ---------------- launch ------------------------------------------------------
extern "C" void kernel_launch(void* const* d_in, const int* in_sizes, int n_in,
                              void* d_out, int out_size) {
    const float* x  = (const float*)d_in[0];
    const float* wg = (const float*)d_in[1];
    const float* w1 = (const float*)d_in[2];
    const float* w3 = (const float*)d_in[3];
    const float* w2 = (const float*)d_in[4];
    float* out = (float*)d_out;

    cudaFuncSetAttribute(gemm13_mma_kernel,
                         cudaFuncAttributeMaxDynamicSharedMemorySize, DSM_GEMM);
    cudaFuncSetAttribute(gemm2_mma_kernel,
                         cudaFuncAttributeMaxDynamicSharedMemorySize, DSM_GEMM);

    prep_kernel<<<MB_TOTAL, 256>>>(x, wg, w1, w3, w2, out);
    select_compact_kernel<<<NEXP, 1024>>>();
    gather_convert_kernel<<<NEXP * CAP / 2, 256>>>(x);
    gemm13_mma_kernel<<<dim3(4096 / 128, CAP / 128, NEXP), 256, DSM_GEMM>>>();
    gemm2_mma_kernel<<<dim3(DIM / 128, CAP / 128, NEXP), 256, DSM_GEMM>>>(out);
}